// round 16
// baseline (speedup 1.0000x reference)
#include <cuda_runtime.h>
#include <cuda_bf16.h>

#define NNODES 1024
#define FIN    256
#define DIN    128
#define DOUT   64
#define BT2    16     // symmetric tile edge
#define MAXP   128    // padded neighbor capacity (deg ~64±7.6; 128 is ~8 sigma)

// Scratch (device globals; no allocation allowed)
__device__ float g_wc[FIN * DOUT];      // lin_w^T @ weight  (256 x 64)
__device__ float g_bias2[DOUT];         // lin_b @ weight
__device__ float g_wf[NNODES * DOUT];   // node embeddings after both linears

// ---------------------------------------------------------------------------
// Wc[f][o] = sum_d lin_w[d][f]*weight[d][o]
// v4: 512-thread blocks, 8-way split-K (16 MAC / thread), smem reduce.
// Block FIN computes bias2 from lin_b the same way.
// ---------------------------------------------------------------------------
__global__ __launch_bounds__(512)
void wc_kernel(const float* __restrict__ lin_w,
               const float* __restrict__ weight,
               const float* __restrict__ lin_b) {
    __shared__ float red[8][DOUT];
    const int o  = threadIdx.x & 63;
    const int dc = threadIdx.x >> 6;        // 0..7
    const int d0 = dc * 16;
    const bool is_bias = (blockIdx.x == FIN);
    const int f = is_bias ? 0 : blockIdx.x;

    float a0 = 0.f, a1 = 0.f, a2 = 0.f, a3 = 0.f;
    #pragma unroll
    for (int d = d0; d < d0 + 16; d += 4) {
        float l0 = is_bias ? lin_b[d]     : lin_w[d * FIN + f];
        float l1 = is_bias ? lin_b[d + 1] : lin_w[(d + 1) * FIN + f];
        float l2 = is_bias ? lin_b[d + 2] : lin_w[(d + 2) * FIN + f];
        float l3 = is_bias ? lin_b[d + 3] : lin_w[(d + 3) * FIN + f];
        a0 = fmaf(l0, weight[d * DOUT + o],       a0);
        a1 = fmaf(l1, weight[(d + 1) * DOUT + o], a1);
        a2 = fmaf(l2, weight[(d + 2) * DOUT + o], a2);
        a3 = fmaf(l3, weight[(d + 3) * DOUT + o], a3);
    }
    red[dc][o] = (a0 + a1) + (a2 + a3);
    __syncthreads();
    if (dc == 0) {
        float v = ((red[0][o] + red[1][o]) + (red[2][o] + red[3][o]))
                + ((red[4][o] + red[5][o]) + (red[6][o] + red[7][o]));
        if (is_bias) g_bias2[o] = v;
        else         g_wc[f * DOUT + o] = v;
    }
}

// ---------------------------------------------------------------------------
// wf[n][o] = sum_f nf[n][f]*Wc[f][o] + bias2[o]
// ---------------------------------------------------------------------------
__global__ __launch_bounds__(256)
void wf_kernel(const float* __restrict__ nf) {
    int gid = blockIdx.x * 256 + threadIdx.x;
    int n = gid >> 6, o = gid & 63;
    const float4* __restrict__ nf4 = (const float4*)(nf + n * FIN);
    float a0 = 0.f, a1 = 0.f, a2 = 0.f, a3 = 0.f;
    #pragma unroll 8
    for (int q = 0; q < FIN / 4; q++) {
        float4 v = nf4[q];
        const float* __restrict__ wc = g_wc + (q * 4) * DOUT + o;
        a0 = fmaf(v.x, wc[0],        a0);
        a1 = fmaf(v.y, wc[DOUT],     a1);
        a2 = fmaf(v.z, wc[2 * DOUT], a2);
        a3 = fmaf(v.w, wc[3 * DOUT], a3);
    }
    g_wf[gid] = ((a0 + a1) + (a2 + a3)) + g_bias2[o];
}

// ---------------------------------------------------------------------------
// out[i,f] = (1/nc[i]^2) * sum_{j,b in N(i)} wf[j,f]*sib[j,b]*wf[b,f]
//
// v5 = v3 + depth-2 gather prefetch: the scattered sib LDG for pair p+2 is
// issued two compute-phases (~250+ cyc) before its s_sib store, covering L2
// latency. Two s_sib buffers remain sufficient (write at p+2 follows p+1's
// barrier, which follows p's reads). Everything else is proven v3:
// inline neighbor build, symmetric column-major pair tiling, wb hoisted per
// B-column (diagonal at fac=1, then wb += wb), branch-free padded gather.
// ---------------------------------------------------------------------------
__global__ __launch_bounds__(256)
void interact_kernel(const float* __restrict__ A,
                     const float* __restrict__ sib,
                     const float* __restrict__ nc,
                     float* __restrict__ out) {
    __shared__ int      s_nbr[MAXP];
    __shared__ unsigned s_mask[32];
    __shared__ int      s_base[33];
    __shared__ __align__(16) float s_wf[MAXP][DOUT];       // 32 KB
    __shared__ __align__(16) float s_sib[2][BT2][BT2];     // 2 KB
    __shared__ float s_part[4][DOUT];

    const int i    = blockIdx.x;
    const int tid  = threadIdx.x;
    const int w    = tid >> 5, lane = tid & 31;

    // ---- build neighbor list from A row i (4 chunks of 256 cols) ----
    bool pr[4];
    #pragma unroll
    for (int c = 0; c < 4; c++) {
        float a = A[i * NNODES + c * 256 + tid];
        pr[c] = (a != 0.0f);
        unsigned m = __ballot_sync(0xffffffffu, pr[c]);
        if (lane == 0) s_mask[c * 8 + w] = m;
    }
    __syncthreads();
    if (tid == 0) {
        int s = 0;
        #pragma unroll
        for (int k = 0; k < 32; k++) { s_base[k] = s; s += __popc(s_mask[k]); }
        s_base[32] = s;
    }
    __syncthreads();
    const unsigned lmask = (1u << lane) - 1u;
    #pragma unroll
    for (int c = 0; c < 4; c++) {
        if (pr[c]) {
            int pos = s_base[c * 8 + w] + __popc(s_mask[c * 8 + w] & lmask);
            if (pos < MAXP) s_nbr[pos] = c * 256 + tid;
        }
    }
    const int deg  = min(s_base[32], MAXP);   // deg >= 1 (self-loop)
    const int T    = (deg + BT2 - 1) / BT2;
    const int degP = T * BT2;
    __syncthreads();

    // pad s_nbr with a valid node index (gather reads stay in-bounds)
    const int n0 = s_nbr[0];
    if (tid < degP - deg) s_nbr[deg + tid] = n0;

    // stage neighbor embeddings, zero-padded to degP rows
    for (int idx = tid; idx < degP * 16; idx += 256) {
        int j = idx >> 4, q = idx & 15;
        float4 v = make_float4(0.f, 0.f, 0.f, 0.f);
        if (j < deg) v = ((const float4*)(g_wf + s_nbr[j] * DOUT))[q];
        ((float4*)(&s_wf[j][0]))[q] = v;
    }
    __syncthreads();   // s_nbr padding + s_wf staging complete

    const int f     = tid & 63;
    const int grp   = tid >> 6;
    const int jr0   = grp * 4;
    const int my_jr = tid >> 4, my_bc = tid & 15;
    float acc = 0.f;
    int  pb  = 0;

    // depth-2 prefetch state: (J2,B2) tracks the pair whose gather is next
    // to ISSUE (i.e. two pairs ahead of the one being stored).
    float pre0, pre1;
    int J2, B2;
    {
        // pair 0 = (J=0,B=0)
        pre0 = sib[(size_t)s_nbr[my_jr] * NNODES + s_nbr[my_bc]];
        // pair 1 (column-major lower triangle after (0,0))
        int J1 = 1, B1 = 0;
        if (J1 >= T) { B1 = 1; J1 = B1; }
        pre1 = (B1 < T)
             ? sib[(size_t)s_nbr[J1 * BT2 + my_jr] * NNODES
                   + s_nbr[B1 * BT2 + my_bc]]
             : 0.f;
        // pair 2
        J2 = J1 + 1; B2 = B1;
        if (J2 >= T) { B2 = B1 + 1; J2 = B2; }
    }

    for (int Bc = 0; Bc < T; Bc++) {
        float wb[BT2];
        #pragma unroll
        for (int bb = 0; bb < BT2; bb++)
            wb[bb] = s_wf[Bc * BT2 + bb][f];      // fac=1 for the diagonal tile

        for (int Jc = Bc; Jc < T; Jc++) {
            s_sib[pb][my_jr][my_bc] = pre0;
            __syncthreads();

            pre0 = pre1;
            if (B2 < T) {                          // issue gather for pair p+2
                pre1 = sib[(size_t)s_nbr[J2 * BT2 + my_jr] * NNODES
                           + s_nbr[B2 * BT2 + my_bc]];
                if (++J2 >= T) { ++B2; J2 = B2; }
            }

            #pragma unroll
            for (int jj = 0; jj < 4; jj++) {
                int r = jr0 + jj;
                const float4* sr = (const float4*)(&s_sib[pb][r][0]);
                float4 a = sr[0], b4 = sr[1], c4 = sr[2], d4 = sr[3];
                float i0 = a.x * wb[0],  i1 = a.y * wb[1];
                float i2 = a.z * wb[2],  i3 = a.w * wb[3];
                i0 = fmaf(b4.x, wb[4],  i0); i1 = fmaf(b4.y, wb[5],  i1);
                i2 = fmaf(b4.z, wb[6],  i2); i3 = fmaf(b4.w, wb[7],  i3);
                i0 = fmaf(c4.x, wb[8],  i0); i1 = fmaf(c4.y, wb[9],  i1);
                i2 = fmaf(c4.z, wb[10], i2); i3 = fmaf(c4.w, wb[11], i3);
                i0 = fmaf(d4.x, wb[12], i0); i1 = fmaf(d4.y, wb[13], i1);
                i2 = fmaf(d4.z, wb[14], i2); i3 = fmaf(d4.w, wb[15], i3);
                float inner = (i0 + i1) + (i2 + i3);
                acc = fmaf(s_wf[Jc * BT2 + r][f], inner, acc);
            }

            if (Jc == Bc) {            // after the diagonal tile: x2 for symmetry
                #pragma unroll
                for (int bb = 0; bb < BT2; bb++) wb[bb] += wb[bb];
            }
            pb ^= 1;
        }
    }

    s_part[grp][f] = acc;
    __syncthreads();
    if (tid < DOUT) {
        float v = s_part[0][tid] + s_part[1][tid] + s_part[2][tid] + s_part[3][tid];
        float c = nc[i];
        out[i * DOUT + tid] = v / (c * c);
    }
}

// ---------------------------------------------------------------------------
// Inputs: 0 node_features, 1 adjacency, 2 mask_father, 3 neighbor_count,
//         4 mask_hadamard(=sib), 5 lin_w, 6 lin_b, 7 weight
// ---------------------------------------------------------------------------
extern "C" void kernel_launch(void* const* d_in, const int* in_sizes, int n_in,
                              void* d_out, int out_size) {
    const float* nf     = (const float*)d_in[0];
    const float* A      = (const float*)d_in[1];
    const float* ncount = (const float*)d_in[3];
    const float* sib    = (const float*)d_in[4];
    const float* lin_w  = (const float*)d_in[5];
    const float* lin_b  = (const float*)d_in[6];
    const float* weight = (const float*)d_in[7];
    float* out = (float*)d_out;

    wc_kernel<<<FIN + 1, 512>>>(lin_w, weight, lin_b);
    wf_kernel<<<(NNODES * DOUT) / 256, 256>>>(nf);
    interact_kernel<<<NNODES, 256>>>(A, sib, ncount, out);
}

// round 17
// speedup vs baseline: 1.0537x; 1.0537x over previous
#include <cuda_runtime.h>
#include <cuda_bf16.h>

#define NNODES 1024
#define FIN    256
#define DIN    128
#define DOUT   64
#define BT2    16     // symmetric tile edge
#define MAXP   128    // padded neighbor capacity (deg ~64±7.6; 128 is ~8 sigma)

// Scratch (device globals; no allocation allowed)
__device__ float g_wc[FIN * DOUT];      // lin_w^T @ weight  (256 x 64)
__device__ float g_bias2[DOUT];         // lin_b @ weight
__device__ float g_wf[NNODES * DOUT];   // node embeddings after both linears

// ---------------------------------------------------------------------------
// Wc[f][o] = sum_d lin_w[d][f]*weight[d][o]
// v4 (measured 5.8us): 512-thread blocks, 8-way split-K (16 MAC / thread),
// smem reduce. Block FIN computes bias2 from lin_b the same way.
// ---------------------------------------------------------------------------
__global__ __launch_bounds__(512)
void wc_kernel(const float* __restrict__ lin_w,
               const float* __restrict__ weight,
               const float* __restrict__ lin_b) {
    __shared__ float red[8][DOUT];
    const int o  = threadIdx.x & 63;
    const int dc = threadIdx.x >> 6;        // 0..7
    const int d0 = dc * 16;
    const bool is_bias = (blockIdx.x == FIN);
    const int f = is_bias ? 0 : blockIdx.x;

    float a0 = 0.f, a1 = 0.f, a2 = 0.f, a3 = 0.f;
    #pragma unroll
    for (int d = d0; d < d0 + 16; d += 4) {
        float l0 = is_bias ? lin_b[d]     : lin_w[d * FIN + f];
        float l1 = is_bias ? lin_b[d + 1] : lin_w[(d + 1) * FIN + f];
        float l2 = is_bias ? lin_b[d + 2] : lin_w[(d + 2) * FIN + f];
        float l3 = is_bias ? lin_b[d + 3] : lin_w[(d + 3) * FIN + f];
        a0 = fmaf(l0, weight[d * DOUT + o],       a0);
        a1 = fmaf(l1, weight[(d + 1) * DOUT + o], a1);
        a2 = fmaf(l2, weight[(d + 2) * DOUT + o], a2);
        a3 = fmaf(l3, weight[(d + 3) * DOUT + o], a3);
    }
    red[dc][o] = (a0 + a1) + (a2 + a3);
    __syncthreads();
    if (dc == 0) {
        float v = ((red[0][o] + red[1][o]) + (red[2][o] + red[3][o]))
                + ((red[4][o] + red[5][o]) + (red[6][o] + red[7][o]));
        if (is_bias) g_bias2[o] = v;
        else         g_wc[f * DOUT + o] = v;
    }
}

// ---------------------------------------------------------------------------
// wf[n][o] = sum_f nf[n][f]*Wc[f][o] + bias2[o]
// ---------------------------------------------------------------------------
__global__ __launch_bounds__(256)
void wf_kernel(const float* __restrict__ nf) {
    int gid = blockIdx.x * 256 + threadIdx.x;
    int n = gid >> 6, o = gid & 63;
    const float4* __restrict__ nf4 = (const float4*)(nf + n * FIN);
    float a0 = 0.f, a1 = 0.f, a2 = 0.f, a3 = 0.f;
    #pragma unroll 8
    for (int q = 0; q < FIN / 4; q++) {
        float4 v = nf4[q];
        const float* __restrict__ wc = g_wc + (q * 4) * DOUT + o;
        a0 = fmaf(v.x, wc[0],        a0);
        a1 = fmaf(v.y, wc[DOUT],     a1);
        a2 = fmaf(v.z, wc[2 * DOUT], a2);
        a3 = fmaf(v.w, wc[3 * DOUT], a3);
    }
    g_wf[gid] = ((a0 + a1) + (a2 + a3)) + g_bias2[o];
}

// ---------------------------------------------------------------------------
// out[i,f] = (1/nc[i]^2) * sum_{j,b in N(i)} wf[j,f]*sib[j,b]*wf[b,f]
//
// v3 EXACTLY as in the 43.7us best run (R15). Both attempted "improvements"
// (f32x2 packing, depth-2 prefetch) measured as regressions and are
// reverted. Inline neighbor build; symmetric column-major pair loop with wb
// hoisted per B-column (diagonal tile at fac=1, then wb += wb);
// double-buffered s_sib -> 1 sync per pair; branch-free padded gather
// (zero-padded s_wf rows annihilate padded contributions).
// ---------------------------------------------------------------------------
__global__ __launch_bounds__(256)
void interact_kernel(const float* __restrict__ A,
                     const float* __restrict__ sib,
                     const float* __restrict__ nc,
                     float* __restrict__ out) {
    __shared__ int      s_nbr[MAXP];
    __shared__ unsigned s_mask[32];
    __shared__ int      s_base[33];
    __shared__ __align__(16) float s_wf[MAXP][DOUT];       // 32 KB
    __shared__ __align__(16) float s_sib[2][BT2][BT2];     // 2 KB
    __shared__ float s_part[4][DOUT];

    const int i    = blockIdx.x;
    const int tid  = threadIdx.x;
    const int w    = tid >> 5, lane = tid & 31;

    // ---- build neighbor list from A row i (4 chunks of 256 cols) ----
    bool pr[4];
    #pragma unroll
    for (int c = 0; c < 4; c++) {
        float a = A[i * NNODES + c * 256 + tid];
        pr[c] = (a != 0.0f);
        unsigned m = __ballot_sync(0xffffffffu, pr[c]);
        if (lane == 0) s_mask[c * 8 + w] = m;
    }
    __syncthreads();
    if (tid == 0) {
        int s = 0;
        #pragma unroll
        for (int k = 0; k < 32; k++) { s_base[k] = s; s += __popc(s_mask[k]); }
        s_base[32] = s;
    }
    __syncthreads();
    const unsigned lmask = (1u << lane) - 1u;
    #pragma unroll
    for (int c = 0; c < 4; c++) {
        if (pr[c]) {
            int pos = s_base[c * 8 + w] + __popc(s_mask[c * 8 + w] & lmask);
            if (pos < MAXP) s_nbr[pos] = c * 256 + tid;
        }
    }
    const int deg  = min(s_base[32], MAXP);   // deg >= 1 (self-loop)
    const int T    = (deg + BT2 - 1) / BT2;
    const int degP = T * BT2;
    __syncthreads();

    // pad s_nbr with a valid node index (gather reads stay in-bounds)
    const int n0 = s_nbr[0];
    if (tid < degP - deg) s_nbr[deg + tid] = n0;

    // stage neighbor embeddings, zero-padded to degP rows
    for (int idx = tid; idx < degP * 16; idx += 256) {
        int j = idx >> 4, q = idx & 15;
        float4 v = make_float4(0.f, 0.f, 0.f, 0.f);
        if (j < deg) v = ((const float4*)(g_wf + s_nbr[j] * DOUT))[q];
        ((float4*)(&s_wf[j][0]))[q] = v;
    }
    __syncthreads();   // s_nbr padding + s_wf staging complete

    const int f     = tid & 63;
    const int grp   = tid >> 6;
    const int jr0   = grp * 4;
    const int my_jr = tid >> 4, my_bc = tid & 15;
    float acc = 0.f;
    int  pb  = 0;

    // prefetch pair (Bc=0, Jc=0)
    float pre = sib[(size_t)s_nbr[my_jr] * NNODES + s_nbr[my_bc]];

    for (int Bc = 0; Bc < T; Bc++) {
        float wb[BT2];
        #pragma unroll
        for (int bb = 0; bb < BT2; bb++)
            wb[bb] = s_wf[Bc * BT2 + bb][f];      // fac=1 for the diagonal tile

        for (int Jc = Bc; Jc < T; Jc++) {
            s_sib[pb][my_jr][my_bc] = pre;
            __syncthreads();

            // prefetch next pair (column-major over the lower triangle)
            int nJ = Jc + 1, nB = Bc;
            if (nJ >= T) { nB = Bc + 1; nJ = nB; }
            if (nB < T)
                pre = sib[(size_t)s_nbr[nJ * BT2 + my_jr] * NNODES
                          + s_nbr[nB * BT2 + my_bc]];

            #pragma unroll
            for (int jj = 0; jj < 4; jj++) {
                int r = jr0 + jj;
                const float4* sr = (const float4*)(&s_sib[pb][r][0]);
                float4 a = sr[0], b4 = sr[1], c4 = sr[2], d4 = sr[3];
                float i0 = a.x * wb[0],  i1 = a.y * wb[1];
                float i2 = a.z * wb[2],  i3 = a.w * wb[3];
                i0 = fmaf(b4.x, wb[4],  i0); i1 = fmaf(b4.y, wb[5],  i1);
                i2 = fmaf(b4.z, wb[6],  i2); i3 = fmaf(b4.w, wb[7],  i3);
                i0 = fmaf(c4.x, wb[8],  i0); i1 = fmaf(c4.y, wb[9],  i1);
                i2 = fmaf(c4.z, wb[10], i2); i3 = fmaf(c4.w, wb[11], i3);
                i0 = fmaf(d4.x, wb[12], i0); i1 = fmaf(d4.y, wb[13], i1);
                i2 = fmaf(d4.z, wb[14], i2); i3 = fmaf(d4.w, wb[15], i3);
                float inner = (i0 + i1) + (i2 + i3);
                acc = fmaf(s_wf[Jc * BT2 + r][f], inner, acc);
            }

            if (Jc == Bc) {            // after the diagonal tile: x2 for symmetry
                #pragma unroll
                for (int bb = 0; bb < BT2; bb++) wb[bb] += wb[bb];
            }
            pb ^= 1;
        }
    }

    s_part[grp][f] = acc;
    __syncthreads();
    if (tid < DOUT) {
        float v = s_part[0][tid] + s_part[1][tid] + s_part[2][tid] + s_part[3][tid];
        float c = nc[i];
        out[i * DOUT + tid] = v / (c * c);
    }
}

// ---------------------------------------------------------------------------
// Inputs: 0 node_features, 1 adjacency, 2 mask_father, 3 neighbor_count,
//         4 mask_hadamard(=sib), 5 lin_w, 6 lin_b, 7 weight
// ---------------------------------------------------------------------------
extern "C" void kernel_launch(void* const* d_in, const int* in_sizes, int n_in,
                              void* d_out, int out_size) {
    const float* nf     = (const float*)d_in[0];
    const float* A      = (const float*)d_in[1];
    const float* ncount = (const float*)d_in[3];
    const float* sib    = (const float*)d_in[4];
    const float* lin_w  = (const float*)d_in[5];
    const float* lin_b  = (const float*)d_in[6];
    const float* weight = (const float*)d_in[7];
    float* out = (float*)d_out;

    wc_kernel<<<FIN + 1, 512>>>(lin_w, weight, lin_b);
    wf_kernel<<<(NNODES * DOUT) / 256, 256>>>(nf);
    interact_kernel<<<NNODES, 256>>>(A, sib, ncount, out);
}